// round 8
// baseline (speedup 1.0000x reference)
#include <cuda_runtime.h>
#include <cuda_bf16.h>

#define BATCH 16
#define NPTS  1024
#define CDIM  64

// -------- scratch (__device__ globals, allocation-free rule) --------
__device__ float         g_r[BATCH * NPTS * CDIM];      // x@W_root + b_rel (fp32)
__device__ __nv_bfloat16 g_yT_hi[BATCH * CDIM * NPTS];  // (x@W_rel)^T hi, [b][c][j]
__device__ __nv_bfloat16 g_yT_lo[BATCH * CDIM * NPTS];  // lo residual

// ===================== helpers =====================
__device__ __forceinline__ unsigned smem_u32(const void* p) {
    unsigned a;
    asm("{ .reg .u64 t; cvta.to.shared.u64 t, %1; cvt.u32.u64 %0, t; }"
        : "=r"(a) : "l"(p));
    return a;
}
#define CP_ASYNC16(dst, src) \
    asm volatile("cp.async.cg.shared.global [%0], [%1], 16;" :: "r"(dst), "l"(src))
#define CP_COMMIT()  asm volatile("cp.async.commit_group;" ::: "memory")
#define STS128(addr, r0, r1, r2, r3) \
    asm volatile("st.shared.v4.b32 [%0], {%1,%2,%3,%4};" \
                 :: "r"(addr), "r"(r0), "r"(r1), "r"(r2), "r"(r3) : "memory")
#define STS128F(addr, r0, r1, r2, r3) \
    asm volatile("st.shared.v4.f32 [%0], {%1,%2,%3,%4};" \
                 :: "r"(addr), "f"(r0), "f"(r1), "f"(r2), "f"(r3) : "memory")
__device__ __forceinline__ float4 lds128f(unsigned a) {
    float4 r;
    asm volatile("ld.shared.v4.f32 {%0,%1,%2,%3}, [%4];"
                 : "=f"(r.x), "=f"(r.y), "=f"(r.z), "=f"(r.w) : "r"(a));
    return r;
}

__device__ __forceinline__ unsigned swz(unsigned off) { return off ^ ((off >> 3) & 0x70); }

__device__ __forceinline__ void ldx4(unsigned* r, unsigned addr) {
    asm volatile("ldmatrix.sync.aligned.m8n8.x4.shared.b16 {%0,%1,%2,%3}, [%4];"
                 : "=r"(r[0]), "=r"(r[1]), "=r"(r[2]), "=r"(r[3]) : "r"(addr));
}
__device__ __forceinline__ void mma16816(float* d, const unsigned* a,
                                         unsigned b0, unsigned b1) {
    asm volatile("mma.sync.aligned.m16n8k16.row.col.f32.bf16.bf16.f32 "
                 "{%0,%1,%2,%3}, {%4,%5,%6,%7}, {%8,%9}, {%0,%1,%2,%3};"
                 : "+f"(d[0]), "+f"(d[1]), "+f"(d[2]), "+f"(d[3])
                 : "r"(a[0]), "r"(a[1]), "r"(a[2]), "r"(a[3]), "r"(b0), "r"(b1));
}
__device__ __forceinline__ float wsel(int e, float w0, float w1, float w2, float w3) {
    return e == 0 ? w0 : (e == 1 ? w1 : (e == 2 ? w2 : w3));
}

// ===================== Stage 1 (unchanged, known-good) =====================
__global__ __launch_bounds__(256) void stage1_kernel(
    const float* __restrict__ x, const float* __restrict__ W_rel,
    const float* __restrict__ b_rel, const float* __restrict__ W_root)
{
    __shared__ float xs[64][64];
    __shared__ float wr[64][64];
    __shared__ float wo[64][64];

    const int tid  = threadIdx.x;
    const int row0 = blockIdx.x * 64;

    for (int t = tid; t < 64 * 16; t += 256) {
        const int r = t >> 4, c4 = (t & 15) << 2;
        *(float4*)&wr[r][c4] = *(const float4*)&W_rel[r * 64 + c4];
        *(float4*)&wo[r][c4] = *(const float4*)&W_root[r * 64 + c4];
    }
    for (int t = tid; t < 64 * 16; t += 256) {
        const int r = t >> 4, c4 = (t & 15) << 2;
        float4 v = *(const float4*)&x[(row0 + r) * 64 + c4];
        xs[c4 + 0][r] = v.x; xs[c4 + 1][r] = v.y;
        xs[c4 + 2][r] = v.z; xs[c4 + 3][r] = v.w;
    }
    __syncthreads();

    const int ty = tid >> 4, tx = tid & 15;
    float accY[4][4] = {}, accR[4][4] = {};

#pragma unroll 8
    for (int k = 0; k < 64; k++) {
        const float4 a  = *(const float4*)&xs[k][ty * 4];
        const float4 by = *(const float4*)&wr[k][tx * 4];
        const float4 br = *(const float4*)&wo[k][tx * 4];
        const float av[4]  = {a.x, a.y, a.z, a.w};
        const float byv[4] = {by.x, by.y, by.z, by.w};
        const float brv[4] = {br.x, br.y, br.z, br.w};
#pragma unroll
        for (int r = 0; r < 4; r++)
#pragma unroll
            for (int c = 0; c < 4; c++) {
                accY[r][c] = fmaf(av[r], byv[c], accY[r][c]);
                accR[r][c] = fmaf(av[r], brv[c], accR[r][c]);
            }
    }

    float4 brel = *(const float4*)&b_rel[tx * 4];
    const float brelv[4] = {brel.x, brel.y, brel.z, brel.w};

    const int b  = row0 >> 10;
    const int jg = (row0 & 1023) + ty * 4;

#pragma unroll
    for (int r = 0; r < 4; r++) {
        const int grow = row0 + ty * 4 + r;
        float4 orr;
        orr.x = accR[r][0] + brelv[0]; orr.y = accR[r][1] + brelv[1];
        orr.z = accR[r][2] + brelv[2]; orr.w = accR[r][3] + brelv[3];
        *(float4*)&g_r[grow * 64 + tx * 4] = orr;
    }
#pragma unroll
    for (int c = 0; c < 4; c++) {
        unsigned hp[2], lp[2];
#pragma unroll
        for (int p = 0; p < 2; p++) {
            float v0 = accY[2 * p + 0][c], v1 = accY[2 * p + 1][c];
            __nv_bfloat16 h0 = __float2bfloat16(v0);
            __nv_bfloat16 h1 = __float2bfloat16(v1);
            __nv_bfloat16 l0 = __float2bfloat16(v0 - __bfloat162float(h0));
            __nv_bfloat16 l1 = __float2bfloat16(v1 - __bfloat162float(h1));
            hp[p] = (unsigned)__bfloat16_as_ushort(h0) | ((unsigned)__bfloat16_as_ushort(h1) << 16);
            lp[p] = (unsigned)__bfloat16_as_ushort(l0) | ((unsigned)__bfloat16_as_ushort(l1) << 16);
        }
        const long idx = ((long)(b * 64 + tx * 4 + c) << 10) + jg;
        *(uint2*)&g_yT_hi[idx] = make_uint2(hp[0], hp[1]);
        *(uint2*)&g_yT_lo[idx] = make_uint2(lp[0], lp[1]);
    }
}

// ===================== Stage 2 =====================
// out[b, i0:i0+64, :] = (adj*we[ea]) @ y + r
// 256 CTAs, 256 threads (8 warps), 2 CTAs/SM.
// Warp tiles 32x32 with K-split: kg = wid>>2 owns k in [kg*32, kg*32+32).
// A: LDG->reg convert->STS bf16 hi/lo, 2 stages. B: cp.async, 3 stages.
#define NCHUNK  16
#define A_ST(t)  (((t) & 1) * 16384)           // hi +0, lo +8192
#define B_ST(t)  (32768 + ((t) % 3) * 16384)   // hi +0, lo +8192
#define SMEM_DYN 81920

__device__ __forceinline__ void issue_B(unsigned sbp, int j0,
                                        const __nv_bfloat16* __restrict__ yhi,
                                        const __nv_bfloat16* __restrict__ ylo,
                                        int tid) {
#pragma unroll
    for (int v = 0; v < 4; v++) {
        const int idx  = tid + v * 256;     // 0..1023 16B slots
        const int tile = idx >> 9;          // 0 hi, 1 lo
        const int row  = (idx >> 3) & 63;   // n (output channel)
        const int cb   = idx & 7;
        const __nv_bfloat16* src =
            (tile ? ylo : yhi) + ((long)row << 10) + j0 + cb * 8;
        CP_ASYNC16(sbp + tile * 8192 + swz(row * 128 + cb * 16), src);
    }
    CP_COMMIT();
}

__global__ __launch_bounds__(256, 2) void stage2_kernel(
    const float* __restrict__ adj, const int* __restrict__ ea,
    const float* __restrict__ w_edge, float* __restrict__ out)
{
    extern __shared__ char smem_raw[];
    const unsigned sb = smem_u32(smem_raw);

    const int tid = threadIdx.x, lane = tid & 31, wid = tid >> 5;
    const int kg = wid >> 2;                  // k group: k in [kg*32, kg*32+32)
    const int wq = wid & 3;
    const int wi = wq & 1, wn = wq >> 1;      // 32-row M half, 32-col N half
    const int b  = blockIdx.x >> 4;
    const int i0 = (blockIdx.x & 15) * 64;

    const float* adj_b = adj + ((long)b << 20);
    const int*   ea_b  = ea  + ((long)b << 20);
    const __nv_bfloat16* yhi = g_yT_hi + ((long)(b * 64) << 10);
    const __nv_bfloat16* ylo = g_yT_lo + ((long)(b * 64) << 10);

    const float w0 = __ldg(w_edge + 0), w1 = __ldg(w_edge + 1),
                w2 = __ldg(w_edge + 2), w3 = __ldg(w_edge + 3);

    // A producer: row = tid>>2 (0..63), cols c0..c0+15 with c0 = (tid&3)*16
    const int  arow = tid >> 2;
    const int  ac0  = (tid & 3) << 4;
    const long rowbase = (long)(i0 + arow) * NPTS + ac0;

    // ldmatrix lane addressing
    const int l8 = lane & 7, mm = lane >> 3;
    const unsigned aRow0 = (unsigned)(wi * 32 + (mm & 1) * 8 + l8) * 128;  // m=0
    const unsigned aColX = ((unsigned)(mm >> 1) * 16) ^ ((unsigned)l8 << 4);
    const unsigned bRow  = (unsigned)(wn * 32 + l8) * 128;
    const unsigned bColX = ((unsigned)kg * 64) ^ ((unsigned)mm * 16) ^ ((unsigned)l8 << 4);

    float acc[2][4][4] = {};          // [m][nt][4]
    float4 pa[4]; int4 pe[4];

    // prologue
    issue_B(sb + B_ST(0), 0,  yhi, ylo, tid);
    issue_B(sb + B_ST(1), 64, yhi, ylo, tid);
#pragma unroll
    for (int q = 0; q < 4; q++) {
        pa[q] = __ldg((const float4*)(adj_b + rowbase + q * 4));
        pe[q] = __ldg((const int4*)(ea_b + rowbase + q * 4));
    }

#pragma unroll 1
    for (int t = 0; t < NCHUNK; t++) {
        // ---- convert A(t) regs -> smem (bf16 hi/lo) ----
        {
            unsigned hp[8], lp[8];
#pragma unroll
            for (int q = 0; q < 4; q++) {
                const float av[4] = {pa[q].x, pa[q].y, pa[q].z, pa[q].w};
                const int   ev[4] = {pe[q].x, pe[q].y, pe[q].z, pe[q].w};
#pragma unroll
                for (int p = 0; p < 2; p++) {
                    float v0 = av[2 * p + 0] * wsel(ev[2 * p + 0], w0, w1, w2, w3);
                    float v1 = av[2 * p + 1] * wsel(ev[2 * p + 1], w0, w1, w2, w3);
                    __nv_bfloat16 h0 = __float2bfloat16(v0);
                    __nv_bfloat16 h1 = __float2bfloat16(v1);
                    __nv_bfloat16 g0 = __float2bfloat16(v0 - __bfloat162float(h0));
                    __nv_bfloat16 g1 = __float2bfloat16(v1 - __bfloat162float(h1));
                    hp[q * 2 + p] = (unsigned)__bfloat16_as_ushort(h0) |
                                    ((unsigned)__bfloat16_as_ushort(h1) << 16);
                    lp[q * 2 + p] = (unsigned)__bfloat16_as_ushort(g0) |
                                    ((unsigned)__bfloat16_as_ushort(g1) << 16);
                }
            }
            const unsigned o0 = sb + A_ST(t) + swz((unsigned)arow * 128 + ac0 * 2);
            const unsigned o1 = sb + A_ST(t) + swz((unsigned)arow * 128 + ac0 * 2 + 16);
            STS128(o0,        hp[0], hp[1], hp[2], hp[3]);
            STS128(o1,        hp[4], hp[5], hp[6], hp[7]);
            STS128(o0 + 8192, lp[0], lp[1], lp[2], lp[3]);
            STS128(o1 + 8192, lp[4], lp[5], lp[6], lp[7]);
        }
        // ---- prefetch A(t+1) ----
        if (t + 1 < NCHUNK) {
            const long src = rowbase + (t + 1) * 64;
#pragma unroll
            for (int q = 0; q < 4; q++) {
                pa[q] = __ldg((const float4*)(adj_b + src + q * 4));
                pe[q] = __ldg((const int4*)(ea_b + src + q * 4));
            }
        }
        // ---- B(t) ready ----
        if (t < NCHUNK - 1) asm volatile("cp.async.wait_group 1;" ::: "memory");
        else                asm volatile("cp.async.wait_group 0;" ::: "memory");
        __syncthreads();
        if (t + 2 < NCHUNK)
            issue_B(sb + B_ST(t + 2), (t + 2) * 64, yhi, ylo, tid);
        // ---- compute chunk t ----
        {
            const unsigned aHi = sb + A_ST(t), aLo = aHi + 8192;
            const unsigned bHi = sb + B_ST(t), bLo = bHi + 8192;
            // B frags: n8 x k32 per ldx4; nt in 0..3 covers warp's 32 n-cols
            unsigned bh[4][4], bl[4][4];
#pragma unroll
            for (int nt = 0; nt < 4; nt++) {
                ldx4(bh[nt], bHi + bRow + nt * 1024 + bColX);
                ldx4(bl[nt], bLo + bRow + nt * 1024 + bColX);
            }
#pragma unroll
            for (int kh = 0; kh < 2; kh++) {
                const unsigned kx = (unsigned)((kg * 2 + kh) * 32);
                unsigned ah[2][4], al[2][4];
#pragma unroll
                for (int m = 0; m < 2; m++) {
                    ldx4(ah[m], aHi + aRow0 + m * 2048 + (kx ^ aColX));
                    ldx4(al[m], aLo + aRow0 + m * 2048 + (kx ^ aColX));
                }
#pragma unroll
                for (int m = 0; m < 2; m++)
#pragma unroll
                    for (int nt = 0; nt < 4; nt++) {
                        mma16816(acc[m][nt], ah[m], bh[nt][2 * kh], bh[nt][2 * kh + 1]);
                        mma16816(acc[m][nt], al[m], bh[nt][2 * kh], bh[nt][2 * kh + 1]);
                        mma16816(acc[m][nt], ah[m], bl[nt][2 * kh], bl[nt][2 * kh + 1]);
                    }
            }
        }
    }

    // ---- K-split reduction: kg=1 stores frag-major into A stage 0, kg=0 adds ----
    // A stage 0 (sb + 0 .. 16384): last readers finished before sync(15).
    const unsigned redbase = sb + (unsigned)wq * 4096 + (unsigned)lane * 16;
    if (kg == 1) {
#pragma unroll
        for (int m = 0; m < 2; m++)
#pragma unroll
            for (int nt = 0; nt < 4; nt++)
                STS128F(redbase + (m * 4 + nt) * 512,
                        acc[m][nt][0], acc[m][nt][1], acc[m][nt][2], acc[m][nt][3]);
    }
    __syncthreads();
    if (kg == 0) {
        const int gid = lane >> 2, tig = lane & 3;
#pragma unroll
        for (int m = 0; m < 2; m++)
#pragma unroll
            for (int nt = 0; nt < 4; nt++) {
                const float4 pv = lds128f(redbase + (m * 4 + nt) * 512);
                const int  grow = b * NPTS + i0 + wi * 32 + m * 16 + gid;
                const int  col  = wn * 32 + nt * 8 + tig * 2;
                const long idx0 = (long)grow * 64 + col;
                const long idx1 = (long)(grow + 8) * 64 + col;
                const float2 r0 = *(const float2*)&g_r[idx0];
                const float2 r1 = *(const float2*)&g_r[idx1];
                float2 o0, o1;
                o0.x = acc[m][nt][0] + pv.x + r0.x;
                o0.y = acc[m][nt][1] + pv.y + r0.y;
                o1.x = acc[m][nt][2] + pv.z + r1.x;
                o1.y = acc[m][nt][3] + pv.w + r1.y;
                *(float2*)&out[idx0] = o0;
                *(float2*)&out[idx1] = o1;
            }
    }
}

// ===================== launch =====================
extern "C" void kernel_launch(void* const* d_in, const int* in_sizes, int n_in,
                              void* d_out, int out_size)
{
    const float* x      = (const float*)d_in[0];
    const float* adj    = (const float*)d_in[1];
    const int*   ea     = (const int*)d_in[2];
    const float* W_rel  = (const float*)d_in[3];
    const float* b_rel  = (const float*)d_in[4];
    const float* W_root = (const float*)d_in[5];
    const float* w_edge = (const float*)d_in[6];
    float* out = (float*)d_out;

    static bool attr_set = false;
    if (!attr_set) {
        cudaFuncSetAttribute(stage2_kernel,
                             cudaFuncAttributeMaxDynamicSharedMemorySize, SMEM_DYN);
        attr_set = true;
    }

    stage1_kernel<<<(BATCH * NPTS) / 64, 256>>>(x, W_rel, b_rel, W_root);
    stage2_kernel<<<BATCH * 16, 256, SMEM_DYN>>>(adj, ea, w_edge, out);
}

// round 9
// speedup vs baseline: 1.1026x; 1.1026x over previous
#include <cuda_runtime.h>
#include <cuda_bf16.h>

#define BATCH 16
#define NPTS  1024
#define CDIM  64

// -------- scratch (__device__ globals, allocation-free rule) --------
__device__ float g_r[BATCH * NPTS * CDIM];    // x@W_root + b_rel (fp32)
__device__ float g_yT[BATCH * CDIM * NPTS];   // (x@W_rel)^T, tf32-rounded, [b][c][j]

// ===================== helpers =====================
__device__ __forceinline__ unsigned smem_u32(const void* p) {
    unsigned a;
    asm("{ .reg .u64 t; cvta.to.shared.u64 t, %1; cvt.u32.u64 %0, t; }"
        : "=r"(a) : "l"(p));
    return a;
}
#define CP_ASYNC16(dst, src) \
    asm volatile("cp.async.cg.shared.global [%0], [%1], 16;" :: "r"(dst), "l"(src))
#define CP_COMMIT()  asm volatile("cp.async.commit_group;" ::: "memory")
#define STS128F(addr, r0, r1, r2, r3) \
    asm volatile("st.shared.v4.f32 [%0], {%1,%2,%3,%4};" \
                 :: "r"(addr), "f"(r0), "f"(r1), "f"(r2), "f"(r3) : "memory")
__device__ __forceinline__ void sts_f(unsigned a, float v) {
    asm volatile("st.shared.f32 [%0], %1;" :: "r"(a), "f"(v) : "memory");
}
__device__ __forceinline__ float lds_f(unsigned a) {
    float r;
    asm volatile("ld.shared.f32 %0, [%1];" : "=f"(r) : "r"(a));
    return r;
}
__device__ __forceinline__ unsigned lds_u(unsigned a) {
    unsigned r;
    asm volatile("ld.shared.b32 %0, [%1];" : "=r"(r) : "r"(a));
    return r;
}
__device__ __forceinline__ float tf32r(float x) {
    unsigned u;
    asm("cvt.rna.tf32.f32 %0, %1;" : "=r"(u) : "f"(x));
    return __uint_as_float(u);
}
__device__ __forceinline__ unsigned tf32u(float x) {
    unsigned u;
    asm("cvt.rna.tf32.f32 %0, %1;" : "=r"(u) : "f"(x));
    return u;
}
__device__ __forceinline__ void mma_tf32(float* d, const unsigned* a,
                                         unsigned b0, unsigned b1) {
    asm volatile("mma.sync.aligned.m16n8k8.row.col.f32.tf32.tf32.f32 "
                 "{%0,%1,%2,%3}, {%4,%5,%6,%7}, {%8,%9}, {%0,%1,%2,%3};"
                 : "+f"(d[0]), "+f"(d[1]), "+f"(d[2]), "+f"(d[3])
                 : "r"(a[0]), "r"(a[1]), "r"(a[2]), "r"(a[3]), "r"(b0), "r"(b1));
}

// ===================== Stage 1 =====================
// y = x@W_rel -> g_yT (transposed, tf32-rounded f32); r = x@W_root + b_rel
__global__ __launch_bounds__(256) void stage1_kernel(
    const float* __restrict__ x, const float* __restrict__ W_rel,
    const float* __restrict__ b_rel, const float* __restrict__ W_root)
{
    __shared__ float xs[64][64];
    __shared__ float wr[64][64];
    __shared__ float wo[64][64];

    const int tid  = threadIdx.x;
    const int row0 = blockIdx.x * 64;

    for (int t = tid; t < 64 * 16; t += 256) {
        const int r = t >> 4, c4 = (t & 15) << 2;
        *(float4*)&wr[r][c4] = *(const float4*)&W_rel[r * 64 + c4];
        *(float4*)&wo[r][c4] = *(const float4*)&W_root[r * 64 + c4];
    }
    for (int t = tid; t < 64 * 16; t += 256) {
        const int r = t >> 4, c4 = (t & 15) << 2;
        float4 v = *(const float4*)&x[(row0 + r) * 64 + c4];
        xs[c4 + 0][r] = v.x; xs[c4 + 1][r] = v.y;
        xs[c4 + 2][r] = v.z; xs[c4 + 3][r] = v.w;
    }
    __syncthreads();

    const int ty = tid >> 4, tx = tid & 15;
    float accY[4][4] = {}, accR[4][4] = {};

#pragma unroll 8
    for (int k = 0; k < 64; k++) {
        const float4 a  = *(const float4*)&xs[k][ty * 4];
        const float4 by = *(const float4*)&wr[k][tx * 4];
        const float4 br = *(const float4*)&wo[k][tx * 4];
        const float av[4]  = {a.x, a.y, a.z, a.w};
        const float byv[4] = {by.x, by.y, by.z, by.w};
        const float brv[4] = {br.x, br.y, br.z, br.w};
#pragma unroll
        for (int r = 0; r < 4; r++)
#pragma unroll
            for (int c = 0; c < 4; c++) {
                accY[r][c] = fmaf(av[r], byv[c], accY[r][c]);
                accR[r][c] = fmaf(av[r], brv[c], accR[r][c]);
            }
    }

    float4 brel = *(const float4*)&b_rel[tx * 4];
    const float brelv[4] = {brel.x, brel.y, brel.z, brel.w};

    const int b  = row0 >> 10;
    const int jg = (row0 & 1023) + ty * 4;

#pragma unroll
    for (int r = 0; r < 4; r++) {
        const int grow = row0 + ty * 4 + r;
        float4 orr;
        orr.x = accR[r][0] + brelv[0]; orr.y = accR[r][1] + brelv[1];
        orr.z = accR[r][2] + brelv[2]; orr.w = accR[r][3] + brelv[3];
        *(float4*)&g_r[grow * 64 + tx * 4] = orr;
    }
    // transposed tf32-rounded writes of y
#pragma unroll
    for (int c = 0; c < 4; c++) {
        const long idx = ((long)(b * 64 + tx * 4 + c) << 10) + jg;
        float4 yv;
        yv.x = tf32r(accY[0][c]); yv.y = tf32r(accY[1][c]);
        yv.z = tf32r(accY[2][c]); yv.w = tf32r(accY[3][c]);
        *(float4*)&g_yT[idx] = yv;
    }
}

// ===================== Stage 2 =====================
// out[b, i0:i0+64, :] = (adj*we[ea]) @ y + r   via single-pass tf32 mma
// 256 CTAs, 512 threads, 2 CTAs/SM. Warp grid 4(M:16) x 4(N:16).
// A: LDG->LUT*adj->tf32 f32 STS, 2 stages x 17408B (64 rows x 68 f32).
// B: cp.async f32, 3 stages x 17408B. j-chunk 64, 16 chunks.
#define NCHUNK   16
#define ROWB     272                     // 68 f32 row stride
#define A_ST(t)  (((t) & 1) * 17408)
#define B_ST(t)  (34816 + ((t) % 3) * 17408)
#define LUT_OFF  87040
#define SMEM_DYN 87072

__device__ __forceinline__ void issue_B(unsigned sbp, int j0,
                                        const float* __restrict__ yT_b, int tid) {
#pragma unroll
    for (int v = 0; v < 2; v++) {
        const int idx  = tid + v * 512;     // 0..1023 16B slots
        const int row  = idx >> 4;          // n (0..63)
        const int slot = idx & 15;
        CP_ASYNC16(sbp + (unsigned)row * ROWB + slot * 16,
                   yT_b + ((long)row << 10) + j0 + slot * 4);
    }
    CP_COMMIT();
}

__global__ __launch_bounds__(512, 2) void stage2_kernel(
    const float* __restrict__ adj, const int* __restrict__ ea,
    const float* __restrict__ w_edge, float* __restrict__ out)
{
    extern __shared__ char smem_raw[];
    const unsigned sb = smem_u32(smem_raw);

    const int tid = threadIdx.x, lane = tid & 31, wid = tid >> 5;
    const int wi = wid & 3, wn = wid >> 2;       // M quarter x N quarter (16 each)
    const int b  = blockIdx.x >> 4;
    const int i0 = (blockIdx.x & 15) * 64;

    const float* adj_b = adj + ((long)b << 20);
    const int*   ea_b  = ea  + ((long)b << 20);
    const float* yT_b  = g_yT + ((long)(b * 64) << 10);

    // w_edge LUT in smem
    const unsigned lut = sb + LUT_OFF;
    if (tid < 4) sts_f(lut + tid * 4, __ldg(w_edge + tid));

    // A producer: row = tid>>3 (0..63), 8 cols at ac0 = (tid&7)*8
    const int  arow = tid >> 3;
    const int  ac0  = (tid & 7) << 3;
    const long rowbase = (long)(i0 + arow) * NPTS + ac0;

    // mma fragment lane addressing (tf32 m16n8k8)
    const unsigned aoff = (unsigned)(wi * 16 + (lane >> 2)) * ROWB +
                          (unsigned)(lane & 3) * 4;
    const unsigned boff = (unsigned)(wn * 16 + (lane >> 2)) * ROWB +
                          (unsigned)(lane & 3) * 4;

    float acc[2][4] = {};
    float4 pa[2]; int4 pe[2];

    __syncthreads();   // LUT visible

    // prologue: B chunks 0,1 in flight; A chunk 0 in regs
    issue_B(sb + B_ST(0), 0,  yT_b, tid);
    issue_B(sb + B_ST(1), 64, yT_b, tid);
#pragma unroll
    for (int q = 0; q < 2; q++) {
        pa[q] = __ldg((const float4*)(adj_b + rowbase + q * 4));
        pe[q] = __ldg((const int4*)(ea_b + rowbase + q * 4));
    }

#pragma unroll 1
    for (int t = 0; t < NCHUNK; t++) {
        // ---- convert A(t): LUT gather + mul + tf32 round -> f32 STS ----
        {
            float v[8];
            const int e[8] = {pe[0].x, pe[0].y, pe[0].z, pe[0].w,
                              pe[1].x, pe[1].y, pe[1].z, pe[1].w};
            const float a[8] = {pa[0].x, pa[0].y, pa[0].z, pa[0].w,
                                pa[1].x, pa[1].y, pa[1].z, pa[1].w};
#pragma unroll
            for (int p = 0; p < 8; p++)
                v[p] = tf32r(a[p] * lds_f(lut + ((unsigned)e[p] << 2)));
            const unsigned o0 = sb + A_ST(t) + (unsigned)arow * ROWB + (unsigned)ac0 * 4;
            STS128F(o0,      v[0], v[1], v[2], v[3]);
            STS128F(o0 + 16, v[4], v[5], v[6], v[7]);
        }
        // ---- prefetch A(t+1) ----
        if (t + 1 < NCHUNK) {
            const long src = rowbase + (t + 1) * 64;
#pragma unroll
            for (int q = 0; q < 2; q++) {
                pa[q] = __ldg((const float4*)(adj_b + src + q * 4));
                pe[q] = __ldg((const int4*)(ea_b + src + q * 4));
            }
        }
        // ---- B(t) ready for all threads ----
        if (t < NCHUNK - 1) asm volatile("cp.async.wait_group 1;" ::: "memory");
        else                asm volatile("cp.async.wait_group 0;" ::: "memory");
        __syncthreads();
        // ---- refill B ring (slot readers done before the sync above) ----
        if (t + 2 < NCHUNK)
            issue_B(sb + B_ST(t + 2), (t + 2) * 64, yT_b, tid);
        // ---- compute chunk t: 8 ksteps x 2 n-tiles ----
        {
            const unsigned aSt = sb + A_ST(t), bSt = sb + B_ST(t);
#pragma unroll
            for (int ks = 0; ks < 8; ks++) {
                const unsigned kb = (unsigned)ks * 32;
                unsigned af[4];
                af[0] = lds_u(aSt + aoff + kb);
                af[1] = lds_u(aSt + aoff + kb + 8 * ROWB);
                af[2] = lds_u(aSt + aoff + kb + 16);
                af[3] = lds_u(aSt + aoff + kb + 8 * ROWB + 16);
#pragma unroll
                for (int nt = 0; nt < 2; nt++) {
                    const unsigned bb = bSt + boff + (unsigned)nt * (8 * ROWB) + kb;
                    const unsigned b0 = lds_u(bb);
                    const unsigned b1 = lds_u(bb + 16);
                    mma_tf32(acc[nt], af, b0, b1);
                }
            }
        }
    }

    // ---- epilogue: add r, store ----
    const int gid = lane >> 2, tig = lane & 3;
    const int grow = b * NPTS + i0 + wi * 16 + gid;
#pragma unroll
    for (int nt = 0; nt < 2; nt++) {
        const int  col  = wn * 16 + nt * 8 + tig * 2;
        const long idx0 = (long)grow * 64 + col;
        const long idx1 = (long)(grow + 8) * 64 + col;
        const float2 r0 = *(const float2*)&g_r[idx0];
        const float2 r1 = *(const float2*)&g_r[idx1];
        float2 o0, o1;
        o0.x = acc[nt][0] + r0.x; o0.y = acc[nt][1] + r0.y;
        o1.x = acc[nt][2] + r1.x; o1.y = acc[nt][3] + r1.y;
        *(float2*)&out[idx0] = o0;
        *(float2*)&out[idx1] = o1;
    }
}

// ===================== launch =====================
extern "C" void kernel_launch(void* const* d_in, const int* in_sizes, int n_in,
                              void* d_out, int out_size)
{
    const float* x      = (const float*)d_in[0];
    const float* adj    = (const float*)d_in[1];
    const int*   ea     = (const int*)d_in[2];
    const float* W_rel  = (const float*)d_in[3];
    const float* b_rel  = (const float*)d_in[4];
    const float* W_root = (const float*)d_in[5];
    const float* w_edge = (const float*)d_in[6];
    float* out = (float*)d_out;

    static bool attr_set = false;
    if (!attr_set) {
        cudaFuncSetAttribute(stage2_kernel,
                             cudaFuncAttributeMaxDynamicSharedMemorySize, SMEM_DYN);
        attr_set = true;
    }

    stage1_kernel<<<(BATCH * NPTS) / 64, 256>>>(x, W_rel, b_rel, W_root);
    stage2_kernel<<<BATCH * 16, 512, SMEM_DYN>>>(adj, ea, w_edge, out);
}